// round 2
// baseline (speedup 1.0000x reference)
#include <cuda_runtime.h>

#define NMAX 50000
#define EMAX 800000
#define DINC 128
#define HH 4
#define CC 32
#define ED 16
#define NEG 0.2f
#define LNEPS 1e-5f

// ---------------- scratch (static device globals; no runtime allocation) ----
__device__ __align__(16) float g_h[(size_t)NMAX * DINC];     // 25.6 MB
__device__ __align__(16) float g_asrc[NMAX * HH];
__device__ __align__(16) float g_adst[NMAX * HH];
__device__ __align__(16) float g_ae[(size_t)EMAX * HH];      // 12.8 MB
__device__ __align__(16) float g_loop[NMAX * ED];            // 3.2 MB
__device__ float g_deg[NMAX];
__device__ __align__(16) float g_denom[NMAX * HH];
__device__ float g_v[ED * HH];
__device__ int g_src[EMAX];
__device__ int g_dst[EMAX];
__device__ int g_is64;

// ---------------- Kdet: detect whether edge_index is int64 or int32 ---------
// int64 view (values < 2^31): int32 view has 0 in every odd slot. Sample 1024.
__global__ void kdetect(const int* __restrict__ ei32, int E) {
    __shared__ int sbad;
    if (threadIdx.x == 0) sbad = 0;
    __syncthreads();
    int stride = (E > 1024) ? (E / 1024) : 1;
    int bad = 0;
    for (int i = threadIdx.x; i < 1024; i += 256) {
        size_t p = (size_t)i * stride;
        if (p < (size_t)E && ei32[2 * p + 1] != 0) bad = 1;
    }
    if (bad) atomicOr(&sbad, 1);
    __syncthreads();
    if (threadIdx.x == 0) g_is64 = sbad ? 0 : 1;
}

// ---------------- Kconv: normalize indices into g_src / g_dst ---------------
__global__ void kconvert(const void* __restrict__ ei, int E) {
    int i = blockIdx.x * blockDim.x + threadIdx.x;
    if (i >= E) return;
    if (g_is64) {
        const long long* p = (const long long*)ei;
        g_src[i] = (int)p[i];
        g_dst[i] = (int)p[(size_t)E + i];
    } else {
        const int* p = (const int*)ei;
        g_src[i] = p[i];
        g_dst[i] = p[(size_t)E + i];
    }
}

// ---------------- K0: v[k][h] = sum_c W_edge[k, h*32+c] * att_edge[h,c] -----
__global__ void k0_precompute_v(const float* __restrict__ W_edge,
                                const float* __restrict__ att_edge) {
    int t = threadIdx.x;           // 64 threads: k = t/4, h = t%4
    if (t >= ED * HH) return;
    int k = t >> 2, h = t & 3;
    float s = 0.f;
    #pragma unroll
    for (int c = 0; c < CC; c++)
        s += W_edge[k * (HH * CC) + h * CC + c] * att_edge[h * CC + c];
    g_v[k * HH + h] = s;
}

// ---------------- Kzero: zero loop_attr and deg -----------------------------
__global__ void kzero(int n) {
    int total = n * ED + n;
    for (int i = blockIdx.x * blockDim.x + threadIdx.x; i < total;
         i += gridDim.x * blockDim.x) {
        if (i < n * ED) g_loop[i] = 0.f;
        else            g_deg[i - n * ED] = 0.f;
    }
}

// ---------------- K1: edge MLP + deg/loop_attr atomics + a_e ---------------
__global__ void k1_edge_mlp(const float* __restrict__ eattr,
                            const float* __restrict__ Wep,
                            const float* __restrict__ bep, int E) {
    __shared__ float sW[ED * ED];
    __shared__ float sb[ED];
    __shared__ float sv[ED * HH];
    __shared__ float sa[256 * 17];   // padded to kill bank conflicts
    int t = threadIdx.x;
    if (t < ED * ED) sW[t] = Wep[t];
    if (t < ED)      sb[t] = bep[t];
    if (t < ED * HH) sv[t] = g_v[t];
    int base = blockIdx.x * 256;
    int cnt = min(256, E - base);
    for (int i = t; i < cnt * ED; i += 256) {
        int r = i / ED, c = i - r * ED;
        sa[r * 17 + c] = eattr[(size_t)base * ED + i];
    }
    __syncthreads();
    int e = base + t;
    if (e >= E) return;

    float ea[ED];
    #pragma unroll
    for (int k = 0; k < ED; k++) ea[k] = sb[k];
    #pragma unroll
    for (int j = 0; j < ED; j++) {
        float a = sa[t * 17 + j];
        #pragma unroll
        for (int k = 0; k < ED; k++) ea[k] += a * sW[j * ED + k];
    }
    #pragma unroll
    for (int k = 0; k < ED; k++) ea[k] = fmaxf(ea[k], 0.f);

    float ae[HH] = {0.f, 0.f, 0.f, 0.f};
    #pragma unroll
    for (int k = 0; k < ED; k++) {
        float a = ea[k];
        #pragma unroll
        for (int h = 0; h < HH; h++) ae[h] += a * sv[k * HH + h];
    }
    int dst = g_dst[e];
    *(float4*)&g_ae[(size_t)e * 4] = make_float4(ae[0], ae[1], ae[2], ae[3]);
    atomicAdd(&g_deg[dst], 1.f);
    float* lp = &g_loop[(size_t)dst * ED];
    #pragma unroll
    for (int q = 0; q < 4; q++) {
        asm volatile("red.global.add.v4.f32 [%0], {%1,%2,%3,%4};" ::
                     "l"(lp + 4 * q),
                     "f"(ea[4 * q + 0]), "f"(ea[4 * q + 1]),
                     "f"(ea[4 * q + 2]), "f"(ea[4 * q + 3]) : "memory");
    }
}

// ---------------- K2: h = x@W_lin, a_src, a_dst -----------------------------
// 256 threads = 8 warps; each warp does 8 rows x 128 cols (thread: 8x4 tile).
__global__ void k2_gemm(const float* __restrict__ x,
                        const float* __restrict__ Wlin,
                        const float* __restrict__ att_src,
                        const float* __restrict__ att_dst, int N) {
    __shared__ float sx[8][8][DINC];   // 32 KB
    int w = threadIdx.x >> 5, lane = threadIdx.x & 31;
    const float4* W4 = (const float4*)Wlin;
    float4 a_s = __ldg((const float4*)&att_src[lane * 4]);
    float4 a_d = __ldg((const float4*)&att_dst[lane * 4]);
    int ngroups = (N + 63) >> 6;
    for (int g = blockIdx.x; g < ngroups; g += gridDim.x) {
        int r0 = g * 64 + w * 8;
        #pragma unroll
        for (int r = 0; r < 8; r++) {
            int n = r0 + r;
            if (n < N)
                *(float4*)&sx[w][r][lane * 4] =
                    __ldg((const float4*)&x[(size_t)n * DINC + lane * 4]);
        }
        __syncwarp();
        float4 acc[8];
        #pragma unroll
        for (int r = 0; r < 8; r++) acc[r] = make_float4(0.f, 0.f, 0.f, 0.f);
        #pragma unroll 4
        for (int k = 0; k < DINC; k++) {
            float4 wv = __ldg(&W4[k * 32 + lane]);
            #pragma unroll
            for (int r = 0; r < 8; r++) {
                float xk = sx[w][r][k];
                acc[r].x += xk * wv.x; acc[r].y += xk * wv.y;
                acc[r].z += xk * wv.z; acc[r].w += xk * wv.w;
            }
        }
        int head = lane >> 3;
        #pragma unroll
        for (int r = 0; r < 8; r++) {
            int n = r0 + r;
            if (n < N) {   // uniform across warp
                *(float4*)&g_h[(size_t)n * DINC + lane * 4] = acc[r];
                float ps = acc[r].x * a_s.x + acc[r].y * a_s.y +
                           acc[r].z * a_s.z + acc[r].w * a_s.w;
                float pd = acc[r].x * a_d.x + acc[r].y * a_d.y +
                           acc[r].z * a_d.z + acc[r].w * a_d.w;
                #pragma unroll
                for (int o = 1; o < 8; o <<= 1) {
                    ps += __shfl_xor_sync(0xffffffffu, ps, o);
                    pd += __shfl_xor_sync(0xffffffffu, pd, o);
                }
                if ((lane & 7) == 0) {
                    g_asrc[n * HH + head] = ps;
                    g_adst[n * HH + head] = pd;
                }
            }
        }
        __syncwarp();
    }
}

// ---------------- K3: self-loop message; initializes out & denom ------------
__global__ void k3_selfloop(float* __restrict__ out, int N) {
    int nb = threadIdx.x >> 7;          // node within block (0..1)
    int t  = threadIdx.x & 127;
    int n  = blockIdx.x * 2 + nb;
    __shared__ float sla[2][ED];
    __shared__ float sv[ED * HH];
    if (threadIdx.x < ED * HH) sv[threadIdx.x] = g_v[threadIdx.x];
    if (n < N && t < ED) {
        float d = fmaxf(g_deg[n], 1.f);
        sla[nb][t] = g_loop[(size_t)n * ED + t] / d;
    }
    __syncthreads();
    if (n >= N) return;
    int head = t >> 5;
    float ael = 0.f;
    #pragma unroll
    for (int k = 0; k < ED; k++) ael += sla[nb][k] * sv[k * HH + head];
    float al = __ldg(&g_asrc[n * HH + head]) + __ldg(&g_adst[n * HH + head]) + ael;
    al = (al >= 0.f) ? al : NEG * al;
    float ex = __expf(al);
    out[(size_t)n * DINC + t] = ex * g_h[(size_t)n * DINC + t];
    if ((t & 31) == 0) g_denom[n * HH + head] = ex;
}

// ---------------- K4: main edge pass (fused exp + scatter) ------------------
// 1 warp per edge; lane handles 4 consecutive output channels.
__global__ void k4_scatter(float* __restrict__ out, int E) {
    int w = (int)((blockIdx.x * (size_t)blockDim.x + threadIdx.x) >> 5);
    int lane = threadIdx.x & 31;
    if (w >= E) return;
    int src = __ldg(&g_src[w]);
    int dst = __ldg(&g_dst[w]);
    float4 ae = __ldg((const float4*)&g_ae[(size_t)w * 4]);
    float4 as = __ldg((const float4*)&g_asrc[(size_t)src * 4]);
    float4 ad = __ldg((const float4*)&g_adst[(size_t)dst * 4]);
    float a0 = as.x + ad.x + ae.x, a1 = as.y + ad.y + ae.y;
    float a2 = as.z + ad.z + ae.z, a3 = as.w + ad.w + ae.w;
    a0 = (a0 >= 0.f) ? a0 : NEG * a0;  a1 = (a1 >= 0.f) ? a1 : NEG * a1;
    a2 = (a2 >= 0.f) ? a2 : NEG * a2;  a3 = (a3 >= 0.f) ? a3 : NEG * a3;
    float e0 = __expf(a0), e1 = __expf(a1), e2 = __expf(a2), e3 = __expf(a3);
    int head = lane >> 3;
    float wgt = (head == 0) ? e0 : (head == 1) ? e1 : (head == 2) ? e2 : e3;
    float4 hv = __ldg((const float4*)&g_h[(size_t)src * DINC + lane * 4]);
    float4 m = make_float4(hv.x * wgt, hv.y * wgt, hv.z * wgt, hv.w * wgt);
    float* op = &out[(size_t)dst * DINC + lane * 4];
    asm volatile("red.global.add.v4.f32 [%0], {%1,%2,%3,%4};" ::
                 "l"(op), "f"(m.x), "f"(m.y), "f"(m.z), "f"(m.w) : "memory");
    if (lane < 4) {
        float ev = (lane == 0) ? e0 : (lane == 1) ? e1 : (lane == 2) ? e2 : e3;
        atomicAdd(&g_denom[(size_t)dst * 4 + lane], ev);
    }
}

// ---------------- K5: normalize + bias + residual + LayerNorm ---------------
__global__ void k5_epilogue(float* __restrict__ out, const float* __restrict__ x,
                            const float* __restrict__ bias,
                            const float* __restrict__ lng,
                            const float* __restrict__ lnb, int N) {
    int nb = threadIdx.x >> 7;
    int t  = threadIdx.x & 127;
    int n  = blockIdx.x * 2 + nb;
    __shared__ float red[2][8];
    bool valid = (n < N);
    float v = 0.f;
    int head = t >> 5;
    if (valid) {
        float den = __ldg(&g_denom[n * HH + head]);
        v = out[(size_t)n * DINC + t] / den + __ldg(&bias[t]) +
            __ldg(&x[(size_t)n * DINC + t]);
    }
    float s = v, s2 = v * v;
    #pragma unroll
    for (int o = 16; o > 0; o >>= 1) {
        s  += __shfl_xor_sync(0xffffffffu, s, o);
        s2 += __shfl_xor_sync(0xffffffffu, s2, o);
    }
    int wi = t >> 5;
    if ((t & 31) == 0) { red[nb][wi] = s; red[nb][4 + wi] = s2; }
    __syncthreads();
    s  = red[nb][0] + red[nb][1] + red[nb][2] + red[nb][3];
    s2 = red[nb][4] + red[nb][5] + red[nb][6] + red[nb][7];
    if (valid) {
        float mu  = s * (1.f / 128.f);
        float var = s2 * (1.f / 128.f) - mu * mu;
        float r = rsqrtf(var + LNEPS);
        out[(size_t)n * DINC + t] = (v - mu) * r * __ldg(&lng[t]) + __ldg(&lnb[t]);
    }
}

// ---------------- launch -----------------------------------------------------
extern "C" void kernel_launch(void* const* d_in, const int* in_sizes, int n_in,
                              void* d_out, int out_size) {
    const float*     x        = (const float*)d_in[0];
    const void*      ei       = (const void*)d_in[1];
    const float*     eattr    = (const float*)d_in[2];
    const float*     Wep      = (const float*)d_in[3];
    const float*     bep      = (const float*)d_in[4];
    const float*     Wlin     = (const float*)d_in[5];
    const float*     Wedge    = (const float*)d_in[6];
    const float*     att_src  = (const float*)d_in[7];
    const float*     att_dst  = (const float*)d_in[8];
    const float*     att_edge = (const float*)d_in[9];
    const float*     bias     = (const float*)d_in[10];
    const float*     lng      = (const float*)d_in[11];
    const float*     lnb      = (const float*)d_in[12];
    float* out = (float*)d_out;

    int N = in_sizes[0] / DINC;          // from x [N,128]  -> dtype-unambiguous
    int E = in_sizes[2] / ED;            // from edge_attr [E,16]

    kdetect<<<1, 256>>>((const int*)ei, E);
    kconvert<<<(E + 255) / 256, 256>>>(ei, E);
    k0_precompute_v<<<1, 64>>>(Wedge, att_edge);
    kzero<<<512, 1024>>>(N);
    k1_edge_mlp<<<(E + 255) / 256, 256>>>(eattr, Wep, bep, E);
    k2_gemm<<<592, 256>>>(x, Wlin, att_src, att_dst, N);
    k3_selfloop<<<(N + 1) / 2, 256>>>(out, N);
    k4_scatter<<<(E + 7) / 8, 256>>>(out, E);
    k5_epilogue<<<(N + 1) / 2, 256>>>(out, x, bias, lng, lnb, N);
}

// round 3
// speedup vs baseline: 1.1386x; 1.1386x over previous
#include <cuda_runtime.h>

#define NMAX 50000
#define EMAX 800000
#define DINC 128
#define HH 4
#define CC 32
#define ED 16
#define NEG 0.2f
#define LNEPS 1e-5f

// ---------------- scratch (static device globals; no runtime allocation) ----
__device__ __align__(16) float g_h[(size_t)NMAX * DINC];     // 25.6 MB
__device__ __align__(16) float g_asrc[NMAX * HH];
__device__ __align__(16) float g_adst[NMAX * HH];
__device__ __align__(16) float g_ae[(size_t)EMAX * HH];      // 12.8 MB
__device__ __align__(16) float g_loop[NMAX * ED];            // 3.2 MB
__device__ float g_deg[NMAX];
__device__ __align__(16) float g_denom[NMAX * HH];
__device__ float g_v[ED * HH];
__device__ __align__(8) int2 g_sd[EMAX];                     // (src,dst) per edge

// ---------------- kzero: zero loop_attr and deg ------------------------------
__global__ void kzero(int n) {
    int total = n * ED + n;
    for (int i = blockIdx.x * blockDim.x + threadIdx.x; i < total;
         i += gridDim.x * blockDim.x) {
        if (i < n * ED) g_loop[i] = 0.f;
        else            g_deg[i - n * ED] = 0.f;
    }
}

// ---------------- kvinit: v[k][h] = sum_c W_edge[k, h*32+c] * att_edge[h,c] --
__global__ void kvinit(const float* __restrict__ W_edge,
                       const float* __restrict__ att_edge) {
    int t = threadIdx.x;           // 64 threads: k = t/4, h = t%4
    if (t >= ED * HH) return;
    int k = t >> 2, h = t & 3;
    float s = 0.f;
    #pragma unroll
    for (int c = 0; c < CC; c++)
        s += W_edge[k * (HH * CC) + h * CC + c] * att_edge[h * CC + c];
    g_v[k * HH + h] = s;
}

// ---------------- K1: edge MLP + dtype detect + deg/loop atomics + a_e ------
__global__ void k1_edge_mlp(const float* __restrict__ eattr,
                            const void* __restrict__ ei,
                            const float* __restrict__ Wep,
                            const float* __restrict__ bep, int E) {
    __shared__ float sW[ED * ED];
    __shared__ float sb[ED];
    __shared__ float sv[ED * HH];
    __shared__ int s_is64;
    int t = threadIdx.x;
    if (t == 0) s_is64 = 1;
    if (t < ED * ED) sW[t] = Wep[t];
    if (t < ED)      sb[t] = bep[t];
    if (t < ED * HH) sv[t] = g_v[t];
    int base = blockIdx.x * 256;
    int e = base + t;
    __syncthreads();
    // dtype probe: for int64 (<2^31) data, odd int32 words of src[] are 0.
    // For genuine int32 data they are random indices (0 w.p. 1/N).
    if (e < E && ((const int*)ei)[2 * e + 1] != 0) s_is64 = 0;
    __syncthreads();
    if (e >= E) return;

    int src, dst;
    if (s_is64) {
        const long long* p = (const long long*)ei;
        src = (int)p[e];
        dst = (int)p[(size_t)E + e];
    } else {
        const int* p = (const int*)ei;
        src = p[e];
        dst = p[(size_t)E + e];
    }
    g_sd[e] = make_int2(src, dst);

    const float4* ap = (const float4*)(eattr + (size_t)e * ED);
    float4 x0 = __ldg(ap + 0), x1 = __ldg(ap + 1);
    float4 x2 = __ldg(ap + 2), x3 = __ldg(ap + 3);
    float xin[ED] = {x0.x, x0.y, x0.z, x0.w, x1.x, x1.y, x1.z, x1.w,
                     x2.x, x2.y, x2.z, x2.w, x3.x, x3.y, x3.z, x3.w};
    float ea[ED];
    #pragma unroll
    for (int k = 0; k < ED; k++) ea[k] = sb[k];
    #pragma unroll
    for (int j = 0; j < ED; j++) {
        float a = xin[j];
        #pragma unroll
        for (int k = 0; k < ED; k++) ea[k] += a * sW[j * ED + k];
    }
    #pragma unroll
    for (int k = 0; k < ED; k++) ea[k] = fmaxf(ea[k], 0.f);

    float ae[HH] = {0.f, 0.f, 0.f, 0.f};
    #pragma unroll
    for (int k = 0; k < ED; k++) {
        float a = ea[k];
        #pragma unroll
        for (int h = 0; h < HH; h++) ae[h] += a * sv[k * HH + h];
    }
    *(float4*)&g_ae[(size_t)e * 4] = make_float4(ae[0], ae[1], ae[2], ae[3]);
    atomicAdd(&g_deg[dst], 1.f);
    float* lp = &g_loop[(size_t)dst * ED];
    #pragma unroll
    for (int q = 0; q < 4; q++) {
        asm volatile("red.global.add.v4.f32 [%0], {%1,%2,%3,%4};" ::
                     "l"(lp + 4 * q),
                     "f"(ea[4 * q + 0]), "f"(ea[4 * q + 1]),
                     "f"(ea[4 * q + 2]), "f"(ea[4 * q + 3]) : "memory");
    }
}

// ---------------- K2: h = x@W_lin, a_src, a_dst -----------------------------
// 256 threads = 8 warps; each warp does 8 rows x 128 cols (thread: 8x4 tile).
__global__ void k2_gemm(const float* __restrict__ x,
                        const float* __restrict__ Wlin,
                        const float* __restrict__ att_src,
                        const float* __restrict__ att_dst, int N) {
    __shared__ __align__(16) float sx[8][8][DINC];   // 32 KB
    int w = threadIdx.x >> 5, lane = threadIdx.x & 31;
    const float4* W4 = (const float4*)Wlin;
    float4 a_s = __ldg((const float4*)&att_src[lane * 4]);
    float4 a_d = __ldg((const float4*)&att_dst[lane * 4]);
    int ngroups = (N + 63) >> 6;
    for (int g = blockIdx.x; g < ngroups; g += gridDim.x) {
        int r0 = g * 64 + w * 8;
        #pragma unroll
        for (int r = 0; r < 8; r++) {
            int n = r0 + r;
            if (n < N)
                *(float4*)&sx[w][r][lane * 4] =
                    __ldg((const float4*)&x[(size_t)n * DINC + lane * 4]);
        }
        __syncwarp();
        float4 acc[8];
        #pragma unroll
        for (int r = 0; r < 8; r++) acc[r] = make_float4(0.f, 0.f, 0.f, 0.f);
        #pragma unroll 2
        for (int kk = 0; kk < DINC; kk += 4) {
            float4 w0 = __ldg(&W4[(kk + 0) * 32 + lane]);
            float4 w1 = __ldg(&W4[(kk + 1) * 32 + lane]);
            float4 w2 = __ldg(&W4[(kk + 2) * 32 + lane]);
            float4 w3 = __ldg(&W4[(kk + 3) * 32 + lane]);
            #pragma unroll
            for (int r = 0; r < 8; r++) {
                float4 xv = *(const float4*)&sx[w][r][kk];   // broadcast LDS.128
                acc[r].x += xv.x * w0.x; acc[r].y += xv.x * w0.y;
                acc[r].z += xv.x * w0.z; acc[r].w += xv.x * w0.w;
                acc[r].x += xv.y * w1.x; acc[r].y += xv.y * w1.y;
                acc[r].z += xv.y * w1.z; acc[r].w += xv.y * w1.w;
                acc[r].x += xv.z * w2.x; acc[r].y += xv.z * w2.y;
                acc[r].z += xv.z * w2.z; acc[r].w += xv.z * w2.w;
                acc[r].x += xv.w * w3.x; acc[r].y += xv.w * w3.y;
                acc[r].z += xv.w * w3.z; acc[r].w += xv.w * w3.w;
            }
        }
        int head = lane >> 3;
        #pragma unroll
        for (int r = 0; r < 8; r++) {
            int n = r0 + r;
            if (n < N) {   // uniform across warp
                *(float4*)&g_h[(size_t)n * DINC + lane * 4] = acc[r];
                float ps = acc[r].x * a_s.x + acc[r].y * a_s.y +
                           acc[r].z * a_s.z + acc[r].w * a_s.w;
                float pd = acc[r].x * a_d.x + acc[r].y * a_d.y +
                           acc[r].z * a_d.z + acc[r].w * a_d.w;
                #pragma unroll
                for (int o = 1; o < 8; o <<= 1) {
                    ps += __shfl_xor_sync(0xffffffffu, ps, o);
                    pd += __shfl_xor_sync(0xffffffffu, pd, o);
                }
                if ((lane & 7) == 0) {
                    g_asrc[n * HH + head] = ps;
                    g_adst[n * HH + head] = pd;
                }
            }
        }
        __syncwarp();
    }
}

// ---------------- K3: self-loop message; initializes out & denom ------------
__global__ void k3_selfloop(float* __restrict__ out, int N) {
    int nb = threadIdx.x >> 7;          // node within block (0..1)
    int t  = threadIdx.x & 127;
    int n  = blockIdx.x * 2 + nb;
    __shared__ float sla[2][ED];
    __shared__ float sv[ED * HH];
    if (threadIdx.x < ED * HH) sv[threadIdx.x] = g_v[threadIdx.x];
    if (n < N && t < ED) {
        float d = fmaxf(g_deg[n], 1.f);
        sla[nb][t] = g_loop[(size_t)n * ED + t] / d;
    }
    __syncthreads();
    if (n >= N) return;
    int head = t >> 5;
    float ael = 0.f;
    #pragma unroll
    for (int k = 0; k < ED; k++) ael += sla[nb][k] * sv[k * HH + head];
    float al = __ldg(&g_asrc[n * HH + head]) + __ldg(&g_adst[n * HH + head]) + ael;
    al = (al >= 0.f) ? al : NEG * al;
    float ex = __expf(al);
    out[(size_t)n * DINC + t] = ex * g_h[(size_t)n * DINC + t];
    if ((t & 31) == 0) g_denom[n * HH + head] = ex;
}

// ---------------- K4: main edge pass (fused exp + scatter) ------------------
// 1 warp per edge; lane handles 4 consecutive output channels.
__global__ void k4_scatter(float* __restrict__ out, int E) {
    int w = (int)((blockIdx.x * (size_t)blockDim.x + threadIdx.x) >> 5);
    int lane = threadIdx.x & 31;
    if (w >= E) return;
    int2 sd = __ldg(&g_sd[w]);
    int src = sd.x, dst = sd.y;
    float4 ae = __ldg((const float4*)&g_ae[(size_t)w * 4]);
    float4 as = __ldg((const float4*)&g_asrc[(size_t)src * 4]);
    float4 ad = __ldg((const float4*)&g_adst[(size_t)dst * 4]);
    float a0 = as.x + ad.x + ae.x, a1 = as.y + ad.y + ae.y;
    float a2 = as.z + ad.z + ae.z, a3 = as.w + ad.w + ae.w;
    a0 = (a0 >= 0.f) ? a0 : NEG * a0;  a1 = (a1 >= 0.f) ? a1 : NEG * a1;
    a2 = (a2 >= 0.f) ? a2 : NEG * a2;  a3 = (a3 >= 0.f) ? a3 : NEG * a3;
    float e0 = __expf(a0), e1 = __expf(a1), e2 = __expf(a2), e3 = __expf(a3);
    int head = lane >> 3;
    float wgt = (head == 0) ? e0 : (head == 1) ? e1 : (head == 2) ? e2 : e3;
    float4 hv = __ldg((const float4*)&g_h[(size_t)src * DINC + lane * 4]);
    float4 m = make_float4(hv.x * wgt, hv.y * wgt, hv.z * wgt, hv.w * wgt);
    float* op = &out[(size_t)dst * DINC + lane * 4];
    asm volatile("red.global.add.v4.f32 [%0], {%1,%2,%3,%4};" ::
                 "l"(op), "f"(m.x), "f"(m.y), "f"(m.z), "f"(m.w) : "memory");
    if (lane == 0) {
        asm volatile("red.global.add.v4.f32 [%0], {%1,%2,%3,%4};" ::
                     "l"(&g_denom[(size_t)dst * 4]),
                     "f"(e0), "f"(e1), "f"(e2), "f"(e3) : "memory");
    }
}

// ---------------- K5: normalize + bias + residual + LayerNorm ---------------
__global__ void k5_epilogue(float* __restrict__ out, const float* __restrict__ x,
                            const float* __restrict__ bias,
                            const float* __restrict__ lng,
                            const float* __restrict__ lnb, int N) {
    int nb = threadIdx.x >> 7;
    int t  = threadIdx.x & 127;
    int n  = blockIdx.x * 2 + nb;
    __shared__ float red[2][8];
    bool valid = (n < N);
    float v = 0.f;
    int head = t >> 5;
    if (valid) {
        float den = __ldg(&g_denom[n * HH + head]);
        v = out[(size_t)n * DINC + t] / den + __ldg(&bias[t]) +
            __ldg(&x[(size_t)n * DINC + t]);
    }
    float s = v, s2 = v * v;
    #pragma unroll
    for (int o = 16; o > 0; o >>= 1) {
        s  += __shfl_xor_sync(0xffffffffu, s, o);
        s2 += __shfl_xor_sync(0xffffffffu, s2, o);
    }
    int wi = t >> 5;
    if ((t & 31) == 0) { red[nb][wi] = s; red[nb][4 + wi] = s2; }
    __syncthreads();
    s  = red[nb][0] + red[nb][1] + red[nb][2] + red[nb][3];
    s2 = red[nb][4] + red[nb][5] + red[nb][6] + red[nb][7];
    if (valid) {
        float mu  = s * (1.f / 128.f);
        float var = s2 * (1.f / 128.f) - mu * mu;
        float r = rsqrtf(var + LNEPS);
        out[(size_t)n * DINC + t] = (v - mu) * r * __ldg(&lng[t]) + __ldg(&lnb[t]);
    }
}

// ---------------- launch -----------------------------------------------------
extern "C" void kernel_launch(void* const* d_in, const int* in_sizes, int n_in,
                              void* d_out, int out_size) {
    const float* x        = (const float*)d_in[0];
    const void*  ei       = (const void*)d_in[1];
    const float* eattr    = (const float*)d_in[2];
    const float* Wep      = (const float*)d_in[3];
    const float* bep      = (const float*)d_in[4];
    const float* Wlin     = (const float*)d_in[5];
    const float* Wedge    = (const float*)d_in[6];
    const float* att_src  = (const float*)d_in[7];
    const float* att_dst  = (const float*)d_in[8];
    const float* att_edge = (const float*)d_in[9];
    const float* bias     = (const float*)d_in[10];
    const float* lng      = (const float*)d_in[11];
    const float* lnb      = (const float*)d_in[12];
    float* out = (float*)d_out;

    int N = in_sizes[0] / DINC;          // from x [N,128]  -> dtype-unambiguous
    int E = in_sizes[2] / ED;            // from edge_attr [E,16]

    kzero<<<512, 1024>>>(N);                                      // 0
    kvinit<<<1, 64>>>(Wedge, att_edge);                           // 1
    k1_edge_mlp<<<(E + 255) / 256, 256>>>(eattr, ei, Wep, bep, E);// 2
    k2_gemm<<<592, 256>>>(x, Wlin, att_src, att_dst, N);          // 3
    k3_selfloop<<<(N + 1) / 2, 256>>>(out, N);                    // 4
    k4_scatter<<<(E + 7) / 8, 256>>>(out, E);                     // 5
    k5_epilogue<<<(N + 1) / 2, 256>>>(out, x, bias, lng, lnb, N); // 6
}